// round 3
// baseline (speedup 1.0000x reference)
#include <cuda_runtime.h>
#include <math.h>

#define BB 16
#define TT 64
#define DD 2304
#define HH 2304
#define GG 9216
#define EE 768
#define LANES 32
#define MAXS 32
#define NSTEPS 31

// Scratch (device globals; no runtime allocation allowed)
__device__ float g_seq[LANES * MAXS * DD];                 // gathered inputs  (9.4 MB)
__device__ float g_xp [LANES * MAXS * GG];                 // precomputed x@W_ih^T + bias (37.7 MB)
__device__ float g_h[2][LANES * HH];                       // double-buffered hidden state
__device__ float g_c[LANES * HH];                          // cell state
__device__ int   g_len[LANES];
__device__ int   g_length[BB];
__device__ int   g_maxlen;
__device__ int   g_rows[LANES * MAXS];                     // packed (lane<<5)|t for valid rows
__device__ int   g_nrows;

// ---------------------------------------------------------------------------
// Kernel 0: lengths, row list, zero states
// ---------------------------------------------------------------------------
__global__ void k_prep(const int* __restrict__ mask,
                       const int* __restrict__ start,
                       const int* __restrict__ end) {
    int tid = threadIdx.x;
    __shared__ int s_len[LANES];
    if (tid < BB) {
        int L = 0;
        for (int t = 0; t < TT; t++) L += mask[tid * TT + t];
        g_length[tid] = L;
        int ll = start[tid] - 1; if (ll < 1) ll = 1;
        int rl = L - end[tid];   if (rl < 1) rl = 1;
        s_len[tid]      = ll;  s_len[BB + tid] = rl;
        g_len[tid]      = ll;  g_len[BB + tid] = rl;
    }
    __syncthreads();
    if (tid == 0) {
        int m = 0, n = 0;
        for (int lane = 0; lane < LANES; lane++) {
            int l = s_len[lane];
            if (l > m) m = l;
            for (int t = 0; t < l; t++) g_rows[n++] = (lane << 5) | t;
        }
        g_maxlen = m;
        g_nrows  = n;
    }
    for (int i = tid; i < LANES * HH; i += blockDim.x) {
        g_h[0][i] = 0.f;
        g_h[1][i] = 0.f;
        g_c[i]    = 0.f;
    }
}

// ---------------------------------------------------------------------------
// Kernel 1: gather left/right sequences (zero-padded), lanes 0..15 left, 16..31 right
// ---------------------------------------------------------------------------
__global__ void k_gather(const float* __restrict__ feat,
                         const int* __restrict__ start,
                         const int* __restrict__ end) {
    int t = blockIdx.x, lane = blockIdx.y;
    if (t >= g_len[lane]) return;
    const float* src = nullptr;
    if (lane < BB) {
        int b = lane;
        if (t + 1 < start[b]) src = feat + ((size_t)b * TT + (t + 1)) * DD;
    } else {
        int b = lane - BB;
        int raw = g_length[b] - end[b];
        if (t < raw) src = feat + ((size_t)b * TT + (end[b] + t)) * DD;
    }
    float4* dst = (float4*)(g_seq + ((size_t)lane * MAXS + t) * DD);
    const float4* s4 = (const float4*)src;
    float4 z = make_float4(0.f, 0.f, 0.f, 0.f);
    for (int i = threadIdx.x; i < DD / 4; i += blockDim.x)
        dst[i] = src ? s4[i] : z;
}

// ---------------------------------------------------------------------------
// Kernel 2: xp GEMM over compact valid-row list.
// M = nrows (<=992, tiled by 128), N = 9216 (tiled by 128), K = 2304 (tiled by 16).
// 256 threads, 8x8 per-thread microtile, float4 smem reads.
// ---------------------------------------------------------------------------
__global__ void __launch_bounds__(256) k_xp(const float* __restrict__ W_ih,
                                            const float* __restrict__ b_ih,
                                            const float* __restrict__ b_hh) {
    int nrows = g_nrows;
    int m0 = blockIdx.y * 128;
    if (m0 >= nrows) return;
    int n0 = blockIdx.x * 128;
    int tid = threadIdx.x;

    __shared__ __align__(16) float As[16 * 132];
    __shared__ __align__(16) float Bs[16 * 132];
    __shared__ int inoff[128];
    __shared__ int outoff[128];

    if (tid < 128) {
        int m  = m0 + tid;
        int rc = (m < nrows) ? g_rows[m] : 0;
        int lane = rc >> 5, t = rc & 31;
        inoff[tid]  = (lane * MAXS + t) * DD;
        outoff[tid] = (lane * MAXS + t) * GG;
    }
    __syncthreads();

    float acc[8][8];
#pragma unroll
    for (int r = 0; r < 8; r++)
#pragma unroll
        for (int c = 0; c < 8; c++) acc[r][c] = 0.f;

    int ty = tid >> 4, tx = tid & 15;

    for (int k0 = 0; k0 < DD; k0 += 16) {
#pragma unroll
        for (int i = 0; i < 2; i++) {
            int flat = tid + i * 256;        // 0..511
            int m = flat >> 2, kq = flat & 3;
            float4 v = *(const float4*)(g_seq + inoff[m] + k0 + kq * 4);
            As[(kq * 4 + 0) * 132 + m] = v.x;
            As[(kq * 4 + 1) * 132 + m] = v.y;
            As[(kq * 4 + 2) * 132 + m] = v.z;
            As[(kq * 4 + 3) * 132 + m] = v.w;
            float4 w = *(const float4*)(W_ih + (size_t)(n0 + m) * DD + k0 + kq * 4);
            Bs[(kq * 4 + 0) * 132 + m] = w.x;
            Bs[(kq * 4 + 1) * 132 + m] = w.y;
            Bs[(kq * 4 + 2) * 132 + m] = w.z;
            Bs[(kq * 4 + 3) * 132 + m] = w.w;
        }
        __syncthreads();
#pragma unroll
        for (int k = 0; k < 16; k++) {
            float4 a0 = *(const float4*)&As[k * 132 + ty * 8];
            float4 a1 = *(const float4*)&As[k * 132 + ty * 8 + 4];
            float4 b0 = *(const float4*)&Bs[k * 132 + tx * 8];
            float4 b1 = *(const float4*)&Bs[k * 132 + tx * 8 + 4];
            float av[8] = {a0.x, a0.y, a0.z, a0.w, a1.x, a1.y, a1.z, a1.w};
            float bv[8] = {b0.x, b0.y, b0.z, b0.w, b1.x, b1.y, b1.z, b1.w};
#pragma unroll
            for (int r = 0; r < 8; r++)
#pragma unroll
                for (int c = 0; c < 8; c++) acc[r][c] += av[r] * bv[c];
        }
        __syncthreads();
    }

#pragma unroll
    for (int r = 0; r < 8; r++) {
        int m = m0 + ty * 8 + r;
        if (m >= nrows) continue;
        int oo = outoff[ty * 8 + r];
#pragma unroll
        for (int c = 0; c < 8; c++) {
            int n = n0 + tx * 8 + c;
            g_xp[(size_t)oo + n] = acc[r][c] + b_ih[n] + b_hh[n];
        }
    }
}

// ---------------------------------------------------------------------------
// Kernel 3: one LSTM step. gates = xp[:,t,:] + h @ W_hh^T, then pointwise.
// Block: 16 hidden units (j) x all 4 gates x all 32 lanes. Grid: 144 blocks.
// h double-buffered across steps (read t&1, write (t&1)^1). Frozen lanes copy h.
// ---------------------------------------------------------------------------
__global__ void __launch_bounds__(128) k_step(int t, const float* __restrict__ W_hh) {
    if (t >= g_maxlen) return;
    int j0 = blockIdx.x * 16;
    int tid = threadIdx.x;
    int lg = tid >> 4;          // 0..7 lane group (4 lanes each)
    int jj = tid & 15;          // hidden unit within tile
    int rb = t & 1, wb = rb ^ 1;

    __shared__ __align__(16) float Hs[32 * 36];      // [k][lane], pad 36
    __shared__ float Ws[4 * 32 * 17];                // [gate][k][j], pad 17

    float acc[4][4];
#pragma unroll
    for (int g = 0; g < 4; g++)
#pragma unroll
        for (int l = 0; l < 4; l++) acc[g][l] = 0.f;

    const float* __restrict__ hsrc = g_h[rb];

    for (int k0 = 0; k0 < HH; k0 += 32) {
#pragma unroll
        for (int i = 0; i < 2; i++) {
            int flat = tid + i * 128;            // 0..255
            int lane = flat >> 3, kq = flat & 7;
            float4 v = *(const float4*)(hsrc + (size_t)lane * HH + k0 + kq * 4);
            Hs[(kq * 4 + 0) * 36 + lane] = v.x;
            Hs[(kq * 4 + 1) * 36 + lane] = v.y;
            Hs[(kq * 4 + 2) * 36 + lane] = v.z;
            Hs[(kq * 4 + 3) * 36 + lane] = v.w;
        }
#pragma unroll
        for (int i = 0; i < 4; i++) {
            int flat = tid + i * 128;            // 0..511
            int kq = flat & 7;
            int rest = flat >> 3;                // 0..63
            int j = rest & 15, gate = rest >> 4;
            float4 v = *(const float4*)(W_hh + (size_t)(gate * HH + j0 + j) * HH + k0 + kq * 4);
            Ws[(gate * 32 + kq * 4 + 0) * 17 + j] = v.x;
            Ws[(gate * 32 + kq * 4 + 1) * 17 + j] = v.y;
            Ws[(gate * 32 + kq * 4 + 2) * 17 + j] = v.z;
            Ws[(gate * 32 + kq * 4 + 3) * 17 + j] = v.w;
        }
        __syncthreads();
#pragma unroll
        for (int k = 0; k < 32; k++) {
            float4 hv = *(const float4*)&Hs[k * 36 + lg * 4];
#pragma unroll
            for (int g = 0; g < 4; g++) {
                float w = Ws[(g * 32 + k) * 17 + jj];
                acc[g][0] += hv.x * w;
                acc[g][1] += hv.y * w;
                acc[g][2] += hv.z * w;
                acc[g][3] += hv.w * w;
            }
        }
        __syncthreads();
    }

    int j = j0 + jj;
#pragma unroll
    for (int ls = 0; ls < 4; ls++) {
        int lane = lg * 4 + ls;
        size_t hidx = (size_t)lane * HH + j;
        float hn = hsrc[hidx];
        if (t < g_len[lane]) {
            const float* xp = g_xp + ((size_t)lane * MAXS + t) * GG;
            float gi  = acc[0][ls] + xp[j];
            float gf  = acc[1][ls] + xp[HH + j];
            float gg_ = acc[2][ls] + xp[2 * HH + j];
            float go  = acc[3][ls] + xp[3 * HH + j];
            float ii = 1.f / (1.f + expf(-gi));
            float ff = 1.f / (1.f + expf(-gf));
            float gt = tanhf(gg_);
            float oo = 1.f / (1.f + expf(-go));
            float c = ff * g_c[hidx] + ii * gt;
            g_c[hidx] = c;
            hn = oo * tanhf(c);
        }
        g_h[wb][hidx] = hn;
    }
}

// ---------------------------------------------------------------------------
// Kernel 4: out = [h_left ; h_right] @ W_out^T + b_out   (16 x 4608 x 768)
// ---------------------------------------------------------------------------
__global__ void __launch_bounds__(256) k_out(const float* __restrict__ W_out,
                                             const float* __restrict__ b_out,
                                             float* __restrict__ out) {
    int e0 = blockIdx.x * 64;
    int tid = threadIdx.x;
    int eL = tid & 63;
    int bg = tid >> 6;              // 0..3 -> batches bg*4..bg*4+3
    int fb = g_maxlen & 1;
    const float* __restrict__ hfin = g_h[fb];

    __shared__ __align__(16) float Fs[32 * 16];   // [k][b]
    __shared__ float Ws[64 * 33];                 // [e][k]

    float acc[4] = {0.f, 0.f, 0.f, 0.f};

    for (int k0 = 0; k0 < 2 * HH; k0 += 32) {
#pragma unroll
        for (int i = 0; i < 2; i++) {
            int flat = tid + i * 256;       // 0..511
            int b = flat & 15, k = flat >> 4;
            int kk = k0 + k;
            float v = (kk < HH) ? hfin[(size_t)b * HH + kk]
                                : hfin[(size_t)(BB + b) * HH + kk - HH];
            Fs[k * 16 + b] = v;
        }
#pragma unroll
        for (int i = 0; i < 8; i++) {
            int flat = tid + i * 256;       // 0..2047
            int e = flat >> 5, k = flat & 31;
            Ws[e * 33 + k] = W_out[(size_t)(e0 + e) * (2 * HH) + k0 + k];
        }
        __syncthreads();
#pragma unroll
        for (int k = 0; k < 32; k++) {
            float w = Ws[eL * 33 + k];
            float4 f = *(const float4*)&Fs[k * 16 + bg * 4];
            acc[0] += w * f.x;
            acc[1] += w * f.y;
            acc[2] += w * f.z;
            acc[3] += w * f.w;
        }
        __syncthreads();
    }

    int e = e0 + eL;
    float bo = b_out[e];
#pragma unroll
    for (int i = 0; i < 4; i++)
        out[(size_t)(bg * 4 + i) * EE + e] = acc[i] + bo;
}

// ---------------------------------------------------------------------------
extern "C" void kernel_launch(void* const* d_in, const int* in_sizes, int n_in,
                              void* d_out, int out_size) {
    const float* feat  = (const float*)d_in[0];
    const int*   mask  = (const int*)  d_in[1];
    const int*   start = (const int*)  d_in[2];
    const int*   end   = (const int*)  d_in[3];
    const float* W_ih  = (const float*)d_in[4];
    const float* W_hh  = (const float*)d_in[5];
    const float* b_ih  = (const float*)d_in[6];
    const float* b_hh  = (const float*)d_in[7];
    const float* W_out = (const float*)d_in[8];
    const float* b_out = (const float*)d_in[9];
    float* out = (float*)d_out;

    k_prep<<<1, 512>>>(mask, start, end);
    k_gather<<<dim3(MAXS, LANES), 256>>>(feat, start, end);
    k_xp<<<dim3(GG / 128, 8), 256>>>(W_ih, b_ih, b_hh);
    for (int t = 0; t < NSTEPS; t++)
        k_step<<<HH / 16, 128>>>(t, W_hh);
    k_out<<<EE / 64, 256>>>(W_out, b_out, out);
}

// round 6
// speedup vs baseline: 2.9335x; 2.9335x over previous
#include <cuda_runtime.h>
#include <math.h>
#include <stdint.h>

#define BB 16
#define TT 64
#define DD 2304
#define HH 2304
#define GG 9216
#define EE 768
#define LANES 32
#define MAXS 32
#define NSTEPS 31
#define KC 144            // K chunks of 16 (2304/16)
#define NTH 144           // step tiles: 16 j x 4 gates = 64 rows each
#define NXB 144           // xp gate blocks of 64

// ---------------- device scratch (no runtime allocation) --------------------
__device__ float g_seq[LANES * MAXS * DD];
__device__ float g_xp [LANES * MAXS * GG];
__device__ float g_h[LANES * HH];            // final h per lane
__device__ float g_c[LANES * HH];
__device__ int   g_len[LANES];
__device__ int   g_length[BB];
__device__ int   g_maxlen;
__device__ int   g_nrows;
__device__ int   g_rows[1024];
// W_hh in A-fragment order: [tile(144)][kc(144)][gate-warp(4)][T*4+a]  (b32)
__device__ uint32_t g_whh_hi[NTH * KC * 4 * 128], g_whh_lo[NTH * KC * 4 * 128];
// W_ih in B-fragment order: [nblk(144)][kc(144)][T(32)][nt(8)*2+b]    (b32)
__device__ uint32_t g_wih_hi[NXB * KC * 32 * 16], g_wih_lo[NXB * KC * 32 * 16];
// seq rows in A-fragment order: [mtile(16)][kc(144)][w(4)][T*4+a]
__device__ uint32_t g_a_hi[16 * KC * 4 * 128], g_a_lo[16 * KC * 4 * 128];
// h in B-fragment order, double buffered: [kc(144)][T(32)][nt(4)*2+b]
__device__ uint32_t g_hBhi[2][KC * 32 * 8], g_hBlo[2][KC * 32 * 8];

// ---------------- helpers ---------------------------------------------------
// split fp32 pair into packed bf16x2 hi and lo (x -> low half)
__device__ __forceinline__ void split2(float x, float y, uint32_t& hi2, uint32_t& lo2) {
    uint32_t h;
    asm("cvt.rn.bf16x2.f32 %0, %1, %2;" : "=r"(h) : "f"(y), "f"(x));
    float fx = __uint_as_float(h << 16);
    float fy = __uint_as_float(h & 0xffff0000u);
    asm("cvt.rn.bf16x2.f32 %0, %1, %2;" : "=r"(lo2) : "f"(y - fy), "f"(x - fx));
    hi2 = h;
}
__device__ __forceinline__ void mma16816(float* c, const uint32_t* a, const uint32_t* b) {
    asm volatile("mma.sync.aligned.m16n8k16.row.col.f32.bf16.bf16.f32 "
        "{%0,%1,%2,%3}, {%4,%5,%6,%7}, {%8,%9}, {%0,%1,%2,%3};"
        : "+f"(c[0]), "+f"(c[1]), "+f"(c[2]), "+f"(c[3])
        : "r"(a[0]), "r"(a[1]), "r"(a[2]), "r"(a[3]), "r"(b[0]), "r"(b[1]));
}
__device__ __forceinline__ float sigm(float x) { return 1.f / (1.f + expf(-x)); }

// ---------------------------------------------------------------------------
// Kernel 0: lengths, compact row list, zero states + hB[0]
// ---------------------------------------------------------------------------
__global__ void k_prep(const int* __restrict__ mask,
                       const int* __restrict__ start,
                       const int* __restrict__ end) {
    int tid = threadIdx.x;
    __shared__ int s_len[LANES];
    if (tid < BB) {
        int L = 0;
        for (int t = 0; t < TT; t++) L += mask[tid * TT + t];
        g_length[tid] = L;
        int ll = start[tid] - 1; if (ll < 1) ll = 1;
        int rl = L - end[tid];   if (rl < 1) rl = 1;
        s_len[tid] = ll;  s_len[BB + tid] = rl;
        g_len[tid] = ll;  g_len[BB + tid] = rl;
    }
    __syncthreads();
    if (tid == 0) {
        int m = 0, n = 0;
        for (int lane = 0; lane < LANES; lane++) {
            int l = s_len[lane];
            if (l > m) m = l;
            for (int t = 0; t < l; t++) g_rows[n++] = (lane << 5) | t;
        }
        g_maxlen = m;
        g_nrows  = n;
    }
    __syncthreads();
    int nr = g_nrows;
    for (int m = nr + tid; m < 1024; m += blockDim.x) g_rows[m] = 0;
    for (int i = tid; i < LANES * HH; i += blockDim.x) { g_h[i] = 0.f; g_c[i] = 0.f; }
    for (int i = tid; i < KC * 32 * 8; i += blockDim.x) {
        g_hBhi[0][i] = 0u;  g_hBlo[0][i] = 0u;
    }
}

// ---------------------------------------------------------------------------
// Kernel 1: gather left/right sequences (zero padded)
// ---------------------------------------------------------------------------
__global__ void k_gather(const float* __restrict__ feat,
                         const int* __restrict__ start,
                         const int* __restrict__ end) {
    int t = blockIdx.x, lane = blockIdx.y;
    if (t >= g_len[lane]) return;
    const float* src = nullptr;
    if (lane < BB) {
        int b = lane;
        if (t + 1 < start[b]) src = feat + ((size_t)b * TT + (t + 1)) * DD;
    } else {
        int b = lane - BB;
        int raw = g_length[b] - end[b];
        if (t < raw) src = feat + ((size_t)b * TT + (end[b] + t)) * DD;
    }
    float4* dst = (float4*)(g_seq + ((size_t)lane * MAXS + t) * DD);
    const float4* s4 = (const float4*)src;
    float4 z = make_float4(0.f, 0.f, 0.f, 0.f);
    for (int i = threadIdx.x; i < DD / 4; i += blockDim.x)
        dst[i] = src ? s4[i] : z;
}

// ---------------------------------------------------------------------------
// Kernel 2: W_hh -> A-fragment order (permuted: tile = j/16, warp = gate)
// ---------------------------------------------------------------------------
__global__ void k_whhprep(const float* __restrict__ W) {
    int r = blockIdx.y;                               // 0..9215 (gate*HH + j)
    int p = blockIdx.x * blockDim.x + threadIdx.x;    // 0..1151
    int k = p * 2;
    int gate = r / HH, j = r - gate * HH;
    int tile = j >> 4, jj = j & 15;
    int kc = k >> 4, kk = k & 15;
    int T = (jj & 7) * 4 + ((kk & 7) >> 1);
    int a = (jj >> 3) + 2 * (kk >> 3);
    float2 v = *(const float2*)(W + (size_t)r * DD + k);
    uint32_t h2, l2; split2(v.x, v.y, h2, l2);
    size_t idx = (((size_t)tile * KC + kc) * 4 + gate) * 128 + T * 4 + a;
    g_whh_hi[idx] = h2;
    g_whh_lo[idx] = l2;
}

// ---------------------------------------------------------------------------
// Kernel 3: W_ih -> B-fragment order
// ---------------------------------------------------------------------------
__global__ void k_wihprep(const float* __restrict__ W) {
    int g = blockIdx.y;                               // gate row 0..9215
    int p = blockIdx.x * blockDim.x + threadIdx.x;
    int k = p * 2;
    int nblk = g >> 6, gg = g & 63;
    int nt = gg >> 3, nn = gg & 7;
    int kc = k >> 4, kk = k & 15;
    int T = nn * 4 + ((kk & 7) >> 1);
    int b = kk >> 3;
    float2 v = *(const float2*)(W + (size_t)g * DD + k);
    uint32_t h2, l2; split2(v.x, v.y, h2, l2);
    size_t idx = (((size_t)nblk * KC + kc) * 32 + T) * 16 + nt * 2 + b;
    g_wih_hi[idx] = h2;
    g_wih_lo[idx] = l2;
}

// ---------------------------------------------------------------------------
// Kernel 4: gathered seq compact rows -> A-fragment order
// ---------------------------------------------------------------------------
__global__ void k_aprep() {
    int m = blockIdx.y;                               // 0..1023
    int p = blockIdx.x * blockDim.x + threadIdx.x;
    int k = p * 2;
    int rc = g_rows[m];
    int lane = rc >> 5, t = rc & 31;
    int mtile = m >> 6, w = (m & 63) >> 4, rr = m & 15;
    int kc = k >> 4, kk = k & 15;
    int T = (rr & 7) * 4 + ((kk & 7) >> 1);
    int a = (rr >> 3) + 2 * (kk >> 3);
    float2 v = *(const float2*)(g_seq + ((size_t)(lane * MAXS + t)) * DD + k);
    uint32_t h2, l2; split2(v.x, v.y, h2, l2);
    size_t idx = (((size_t)mtile * KC + kc) * 4 + w) * 128 + T * 4 + a;
    g_a_hi[idx] = h2;
    g_a_lo[idx] = l2;
}

// ---------------------------------------------------------------------------
// Kernel 5: xp GEMM via mma.sync. grid (144 nblk, 16 mtile), block 128.
// ---------------------------------------------------------------------------
__global__ void __launch_bounds__(128) k_xp_mma(const float* __restrict__ b_ih,
                                                const float* __restrict__ b_hh) {
    int nrows = g_nrows;
    int m0 = blockIdx.y * 64;
    if (m0 >= nrows) return;
    int nblk = blockIdx.x;
    int tid = threadIdx.x, w = tid >> 5, T = tid & 31;

    __shared__ int soff[64];
    if (tid < 64) {
        int rc = g_rows[m0 + tid];
        soff[tid] = ((rc >> 5) * MAXS + (rc & 31)) * GG;
    }
    __syncthreads();

    const uint4* Ah = (const uint4*)g_a_hi  + (((size_t)(m0 >> 6) * KC) * 4 + w) * 32 + T;
    const uint4* Al = (const uint4*)g_a_lo  + (((size_t)(m0 >> 6) * KC) * 4 + w) * 32 + T;
    const uint4* Bh = (const uint4*)g_wih_hi + (((size_t)nblk * KC) * 32 + T) * 4;
    const uint4* Bl = (const uint4*)g_wih_lo + (((size_t)nblk * KC) * 32 + T) * 4;

    float acc[8][4];
#pragma unroll
    for (int i = 0; i < 8; i++)
#pragma unroll
        for (int r = 0; r < 4; r++) acc[i][r] = 0.f;

    uint4 ah[2], al[2], bh[2][4], bl[2][4];
#pragma unroll
    for (int q = 0; q < 4; q++) { bh[0][q] = Bh[q]; bl[0][q] = Bl[q]; }
    ah[0] = Ah[0]; al[0] = Al[0];

    for (int kc = 0; kc < KC; kc++) {
        int cur = kc & 1, nxt = cur ^ 1;
        if (kc + 1 < KC) {
            ah[nxt] = Ah[(size_t)(kc + 1) * 128];
            al[nxt] = Al[(size_t)(kc + 1) * 128];
#pragma unroll
            for (int q = 0; q < 4; q++) {
                bh[nxt][q] = Bh[(size_t)(kc + 1) * 128 + q];
                bl[nxt][q] = Bl[(size_t)(kc + 1) * 128 + q];
            }
        }
        const uint32_t* Ahr = (const uint32_t*)&ah[cur];
        const uint32_t* Alr = (const uint32_t*)&al[cur];
        const uint32_t* Bhr = (const uint32_t*)&bh[cur][0];
        const uint32_t* Blr = (const uint32_t*)&bl[cur][0];
#pragma unroll
        for (int nt = 0; nt < 8; nt++) {
            mma16816(acc[nt], Ahr, Bhr + nt * 2);
            mma16816(acc[nt], Ahr, Blr + nt * 2);
            mma16816(acc[nt], Alr, Bhr + nt * 2);
        }
    }

#pragma unroll
    for (int nt = 0; nt < 8; nt++)
#pragma unroll
        for (int r = 0; r < 4; r++) {
            int ml = w * 16 + (T >> 2) + 8 * (r >> 1);
            if (m0 + ml < nrows) {
                int col = nblk * 64 + nt * 8 + 2 * (T & 3) + (r & 1);
                g_xp[(size_t)soff[ml] + col] = acc[nt][r] + b_ih[col] + b_hh[col];
            }
        }
}

// ---------------------------------------------------------------------------
// Kernel 6: one LSTM step via mma.sync. grid 144, block 256.
// Warps 0-3: gates 0-3 over kc [0,72). Warps 4-7: gates 0-3 over kc [72,144).
// Partial D reduced via SMEM. D = W_hh_perm[64 x 2304] @ h[2304 x 32].
// ---------------------------------------------------------------------------
#define KH 72
__global__ void __launch_bounds__(256) k_step_mma(int t) {
    if (t >= g_maxlen) return;
    int tile = blockIdx.x;
    int tid = threadIdx.x, w = tid >> 5, T = tid & 31;
    int gate = w & 3, kh = w >> 2;
    int rb = t & 1, wb = rb ^ 1;

    __shared__ float gsm[64 * 33];

    const uint4* Ah = (const uint4*)g_whh_hi + (((size_t)tile * KC + kh * KH) * 4 + gate) * 32 + T;
    const uint4* Al = (const uint4*)g_whh_lo + (((size_t)tile * KC + kh * KH) * 4 + gate) * 32 + T;
    const uint4* Bh = (const uint4*)g_hBhi[rb] + (size_t)kh * KH * 64 + T * 2;
    const uint4* Bl = (const uint4*)g_hBlo[rb] + (size_t)kh * KH * 64 + T * 2;

    float acc[4][4];
#pragma unroll
    for (int i = 0; i < 4; i++)
#pragma unroll
        for (int r = 0; r < 4; r++) acc[i][r] = 0.f;

    uint4 ah[2], al[2], bh[2][2], bl[2][2];
    ah[0] = Ah[0]; al[0] = Al[0];
    bh[0][0] = Bh[0]; bh[0][1] = Bh[1];
    bl[0][0] = Bl[0]; bl[0][1] = Bl[1];

    for (int i = 0; i < KH; i++) {
        int cur = i & 1, nxt = cur ^ 1;
        if (i + 1 < KH) {
            size_t ao = (size_t)(i + 1) * 128;
            size_t bo = (size_t)(i + 1) * 64;
            ah[nxt] = Ah[ao];
            al[nxt] = Al[ao];
            bh[nxt][0] = Bh[bo];     bh[nxt][1] = Bh[bo + 1];
            bl[nxt][0] = Bl[bo];     bl[nxt][1] = Bl[bo + 1];
        }
        const uint32_t* Ahr = (const uint32_t*)&ah[cur];
        const uint32_t* Alr = (const uint32_t*)&al[cur];
        const uint32_t* Bhr = (const uint32_t*)&bh[cur][0];
        const uint32_t* Blr = (const uint32_t*)&bl[cur][0];
#pragma unroll
        for (int nt = 0; nt < 4; nt++) {
            mma16816(acc[nt], Ahr, Bhr + nt * 2);
            mma16816(acc[nt], Ahr, Blr + nt * 2);
            mma16816(acc[nt], Alr, Bhr + nt * 2);
        }
    }

    // reduce K halves: kh=1 stores, kh=0 adds
    if (kh == 1) {
#pragma unroll
        for (int nt = 0; nt < 4; nt++)
#pragma unroll
            for (int r = 0; r < 4; r++) {
                int rr = (T >> 2) + 8 * (r >> 1);
                int lane = nt * 8 + 2 * (T & 3) + (r & 1);
                gsm[(gate * 16 + rr) * 33 + lane] = acc[nt][r];
            }
    }
    __syncthreads();
    if (kh == 0) {
#pragma unroll
        for (int nt = 0; nt < 4; nt++)
#pragma unroll
            for (int r = 0; r < 4; r++) {
                int rr = (T >> 2) + 8 * (r >> 1);
                int lane = nt * 8 + 2 * (T & 3) + (r & 1);
                gsm[(gate * 16 + rr) * 33 + lane] += acc[nt][r];
            }
    }
    __syncthreads();

    // pointwise + repack h into B-fragment layout for next step (256 thr = 32 lanes x 8 jp)
    {
        int p = tid;
        int lane = p >> 3, jp = p & 7;
        int jj0 = jp * 2;
        int Tt = (lane & 7) * 4 + ((jj0 & 7) >> 1);
        int nt = lane >> 3, b = jj0 >> 3;
        int idx = tile * 256 + Tt * 8 + nt * 2 + b;
        if (t < g_len[lane]) {
            float hv[2];
            const float* xp = g_xp + ((size_t)(lane * MAXS + t)) * GG;
#pragma unroll
            for (int q = 0; q < 2; q++) {
                int jj = jj0 + q;
                int j = tile * 16 + jj;
                float gi = gsm[(0 * 16 + jj) * 33 + lane] + xp[j];
                float gf = gsm[(1 * 16 + jj) * 33 + lane] + xp[HH + j];
                float gg = gsm[(2 * 16 + jj) * 33 + lane] + xp[2 * HH + j];
                float go = gsm[(3 * 16 + jj) * 33 + lane] + xp[3 * HH + j];
                size_t ci = (size_t)lane * HH + j;
                float cc = sigm(gf) * g_c[ci] + sigm(gi) * tanhf(gg);
                g_c[ci] = cc;
                float h = sigm(go) * tanhf(cc);
                g_h[ci] = h;
                hv[q] = h;
            }
            uint32_t h2, l2; split2(hv[0], hv[1], h2, l2);
            g_hBhi[wb][idx] = h2;
            g_hBlo[wb][idx] = l2;
        } else {
            g_hBhi[wb][idx] = g_hBhi[rb][idx];
            g_hBlo[wb][idx] = g_hBlo[rb][idx];
        }
    }
}

// ---------------------------------------------------------------------------
// Kernel 7: out = [h_left ; h_right] @ W_out^T + b_out
// ---------------------------------------------------------------------------
__global__ void __launch_bounds__(256) k_out(const float* __restrict__ W_out,
                                             const float* __restrict__ b_out,
                                             float* __restrict__ out) {
    int e0 = blockIdx.x * 64;
    int tid = threadIdx.x;
    int eL = tid & 63;
    int bg = tid >> 6;

    __shared__ __align__(16) float Fs[32 * 16];
    __shared__ float Ws[64 * 33];
    float acc[4] = {0.f, 0.f, 0.f, 0.f};

    for (int k0 = 0; k0 < 2 * HH; k0 += 32) {
#pragma unroll
        for (int i = 0; i < 2; i++) {
            int flat = tid + i * 256;
            int b = flat & 15, k = flat >> 4;
            int kk = k0 + k;
            float v = (kk < HH) ? g_h[(size_t)b * HH + kk]
                                : g_h[(size_t)(BB + b) * HH + kk - HH];
            Fs[k * 16 + b] = v;
        }
#pragma unroll
        for (int i = 0; i < 8; i++) {
            int flat = tid + i * 256;
            int e = flat >> 5, k = flat & 31;
            Ws[e * 33 + k] = W_out[(size_t)(e0 + e) * (2 * HH) + k0 + k];
        }
        __syncthreads();
#pragma unroll
        for (int k = 0; k < 32; k++) {
            float wv = Ws[eL * 33 + k];
            float4 f = *(const float4*)&Fs[k * 16 + bg * 4];
            acc[0] += wv * f.x;  acc[1] += wv * f.y;
            acc[2] += wv * f.z;  acc[3] += wv * f.w;
        }
        __syncthreads();
    }
    int e = e0 + eL;
    float bo = b_out[e];
#pragma unroll
    for (int i = 0; i < 4; i++)
        out[(size_t)(bg * 4 + i) * EE + e] = acc[i] + bo;
}

// ---------------------------------------------------------------------------
extern "C" void kernel_launch(void* const* d_in, const int* in_sizes, int n_in,
                              void* d_out, int out_size) {
    const float* feat  = (const float*)d_in[0];
    const int*   mask  = (const int*)  d_in[1];
    const int*   start = (const int*)  d_in[2];
    const int*   end   = (const int*)  d_in[3];
    const float* W_ih  = (const float*)d_in[4];
    const float* W_hh  = (const float*)d_in[5];
    const float* b_ih  = (const float*)d_in[6];
    const float* b_hh  = (const float*)d_in[7];
    const float* W_out = (const float*)d_in[8];
    const float* b_out = (const float*)d_in[9];
    float* out = (float*)d_out;

    k_prep<<<1, 512>>>(mask, start, end);
    k_gather<<<dim3(MAXS, LANES), 256>>>(feat, start, end);
    k_whhprep<<<dim3(9, GG), 128>>>(W_hh);
    k_wihprep<<<dim3(9, GG), 128>>>(W_ih);
    k_aprep<<<dim3(9, 1024), 128>>>();
    k_xp_mma<<<dim3(NXB, 16), 128>>>(b_ih, b_hh);
    for (int t = 0; t < NSTEPS; t++)
        k_step_mma<<<NTH, 256>>>(t);
    k_out<<<EE / 64, 256>>>(W_out, b_out, out);
}

// round 7
// speedup vs baseline: 3.3600x; 1.1454x over previous
#include <cuda_runtime.h>
#include <math.h>
#include <stdint.h>

#define BB 16
#define TT 64
#define DD 2304
#define HH 2304
#define GG 9216
#define EE 768
#define LANES 32
#define MAXS 32
#define NSTEPS 31
#define KC 144            // K chunks of 16 (2304/16)
#define NTH 144           // step tiles: 16 j x 4 gates = 64 rows each
#define NXB 144           // xp gate blocks of 64
#define KH4 36            // chunks per k-split quarter

// ---------------- device scratch (no runtime allocation) --------------------
__device__ float g_xp [LANES * MAXS * GG];
__device__ float g_h[LANES * HH];            // final h per lane
__device__ float g_c[LANES * HH];
__device__ int   g_len[LANES];
__device__ int   g_length[BB];
__device__ int   g_maxlen;
__device__ int   g_nrows;
__device__ int   g_rows[1024];
// W_hh in A-fragment order: [tile(144)][kc(144)][gate-warp(4)][T*4+a]  (b32)
__device__ uint32_t g_whh_hi[NTH * KC * 4 * 128], g_whh_lo[NTH * KC * 4 * 128];
// W_ih in B-fragment order: [nblk(144)][kc(144)][T(32)][nt(8)*2+b]    (b32)
__device__ uint32_t g_wih_hi[NXB * KC * 32 * 16], g_wih_lo[NXB * KC * 32 * 16];
// seq rows in A-fragment order: [mtile(16)][kc(144)][w(4)][T*4+a]
__device__ uint32_t g_a_hi[16 * KC * 4 * 128], g_a_lo[16 * KC * 4 * 128];
// h in B-fragment order, double buffered: [kc(144)][T(32)][nt(4)*2+b]
__device__ uint32_t g_hBhi[2][KC * 32 * 8], g_hBlo[2][KC * 32 * 8];

// ---------------- helpers ---------------------------------------------------
// split fp32 pair into packed bf16x2 hi and lo (x -> low half)
__device__ __forceinline__ void split2(float x, float y, uint32_t& hi2, uint32_t& lo2) {
    uint32_t h;
    asm("cvt.rn.bf16x2.f32 %0, %1, %2;" : "=r"(h) : "f"(y), "f"(x));
    float fx = __uint_as_float(h << 16);
    float fy = __uint_as_float(h & 0xffff0000u);
    asm("cvt.rn.bf16x2.f32 %0, %1, %2;" : "=r"(lo2) : "f"(y - fy), "f"(x - fx));
    hi2 = h;
}
__device__ __forceinline__ void mma16816(float* c, const uint32_t* a, const uint32_t* b) {
    asm volatile("mma.sync.aligned.m16n8k16.row.col.f32.bf16.bf16.f32 "
        "{%0,%1,%2,%3}, {%4,%5,%6,%7}, {%8,%9}, {%0,%1,%2,%3};"
        : "+f"(c[0]), "+f"(c[1]), "+f"(c[2]), "+f"(c[3])
        : "r"(a[0]), "r"(a[1]), "r"(a[2]), "r"(a[3]), "r"(b[0]), "r"(b[1]));
}
__device__ __forceinline__ float sigm(float x) { return 1.f / (1.f + expf(-x)); }

// ---------------------------------------------------------------------------
// Kernel 0: lengths, compact row list, zero states + hB[0]
// ---------------------------------------------------------------------------
__global__ void k_prep(const int* __restrict__ mask,
                       const int* __restrict__ start,
                       const int* __restrict__ end) {
    int tid = threadIdx.x;
    __shared__ int s_len[LANES];
    if (tid < BB) {
        int L = 0;
        for (int t = 0; t < TT; t++) L += mask[tid * TT + t];
        g_length[tid] = L;
        int ll = start[tid] - 1; if (ll < 1) ll = 1;
        int rl = L - end[tid];   if (rl < 1) rl = 1;
        s_len[tid] = ll;  s_len[BB + tid] = rl;
        g_len[tid] = ll;  g_len[BB + tid] = rl;
    }
    __syncthreads();
    if (tid == 0) {
        int m = 0, n = 0;
        for (int lane = 0; lane < LANES; lane++) {
            int l = s_len[lane];
            if (l > m) m = l;
            for (int t = 0; t < l; t++) g_rows[n++] = (lane << 5) | t;
        }
        g_maxlen = m;
        g_nrows  = n;
    }
    __syncthreads();
    int nr = g_nrows;
    for (int m = nr + tid; m < 1024; m += blockDim.x) g_rows[m] = 0;
    for (int i = tid; i < LANES * HH; i += blockDim.x) { g_h[i] = 0.f; g_c[i] = 0.f; }
    for (int i = tid; i < KC * 32 * 8; i += blockDim.x) {
        g_hBhi[0][i] = 0u;  g_hBlo[0][i] = 0u;
    }
}

// ---------------------------------------------------------------------------
// Kernel 1: W_hh -> A-fragment order, coalesced writes.
// grid (KC, NTH), block 128: warp = gate, thread T writes uint4 (T*4+a, a=0..3)
// ---------------------------------------------------------------------------
__global__ void __launch_bounds__(128) k_whhprep(const float* __restrict__ W) {
    int kc = blockIdx.x, tile = blockIdx.y;
    int tid = threadIdx.x, gate = tid >> 5, T = tid & 31;
    uint32_t hi4[4], lo4[4];
#pragma unroll
    for (int a = 0; a < 4; a++) {
        int jj = (a & 1) * 8 + (T >> 2);
        int kk = (a >> 1) * 8 + (T & 3) * 2;
        int r = gate * HH + tile * 16 + jj;
        float2 v = *(const float2*)(W + (size_t)r * DD + kc * 16 + kk);
        split2(v.x, v.y, hi4[a], lo4[a]);
    }
    size_t idx = (((size_t)tile * KC + kc) * 4 + gate) * 128 + T * 4;
    *(uint4*)&g_whh_hi[idx] = *(uint4*)hi4;
    *(uint4*)&g_whh_lo[idx] = *(uint4*)lo4;
}

// ---------------------------------------------------------------------------
// Kernel 2: W_ih -> B-fragment order, coalesced writes.
// grid (KC, NXB), block 128: thread tid writes uint4 at chunk-base + tid*4
// ---------------------------------------------------------------------------
__global__ void __launch_bounds__(128) k_wihprep(const float* __restrict__ W) {
    int kc = blockIdx.x, nblk = blockIdx.y;
    int tid = threadIdx.x;
    int T = tid >> 2;
    uint32_t hi4[4], lo4[4];
#pragma unroll
    for (int i = 0; i < 4; i++) {
        int r = (tid & 3) * 4 + i;
        int nt = r >> 1, b = r & 1;
        int g = nblk * 64 + nt * 8 + (T >> 2);
        int kk = b * 8 + (T & 3) * 2;
        float2 v = *(const float2*)(W + (size_t)g * DD + kc * 16 + kk);
        split2(v.x, v.y, hi4[i], lo4[i]);
    }
    size_t idx = ((size_t)nblk * KC + kc) * 512 + tid * 4;
    *(uint4*)&g_wih_hi[idx] = *(uint4*)hi4;
    *(uint4*)&g_wih_lo[idx] = *(uint4*)lo4;
}

// ---------------------------------------------------------------------------
// Kernel 3: fused gather + fragment pack of compact seq rows (reads feat)
// grid (9, 1024), block 128. thread = (row m, k-pair)
// ---------------------------------------------------------------------------
__global__ void k_aprep(const float* __restrict__ feat,
                        const int* __restrict__ start,
                        const int* __restrict__ end) {
    int m = blockIdx.y;
    int p = blockIdx.x * blockDim.x + threadIdx.x;
    int k = p * 2;
    int rc = g_rows[m];
    int lane = rc >> 5, t = rc & 31;
    const float* src = nullptr;
    if (lane < BB) {
        int b = lane;
        if (t + 1 < start[b]) src = feat + ((size_t)b * TT + (t + 1)) * DD;
    } else {
        int b = lane - BB;
        int raw = g_length[b] - end[b];
        if (t < raw) src = feat + ((size_t)b * TT + (end[b] + t)) * DD;
    }
    float2 v = make_float2(0.f, 0.f);
    if (src) v = *(const float2*)(src + k);
    int mtile = m >> 6, w = (m & 63) >> 4, rr = m & 15;
    int kc = k >> 4, kk = k & 15;
    int T = (rr & 7) * 4 + ((kk & 7) >> 1);
    int a = (rr >> 3) + 2 * (kk >> 3);
    uint32_t h2, l2; split2(v.x, v.y, h2, l2);
    size_t idx = (((size_t)mtile * KC + kc) * 4 + w) * 128 + T * 4 + a;
    g_a_hi[idx] = h2;
    g_a_lo[idx] = l2;
}

// ---------------------------------------------------------------------------
// Kernel 4: xp GEMM via mma.sync. grid (144 nblk, 16 mtile), block 128.
// ---------------------------------------------------------------------------
__global__ void __launch_bounds__(128) k_xp_mma(const float* __restrict__ b_ih,
                                                const float* __restrict__ b_hh) {
    int nrows = g_nrows;
    int m0 = blockIdx.y * 64;
    if (m0 >= nrows) return;
    int nblk = blockIdx.x;
    int tid = threadIdx.x, w = tid >> 5, T = tid & 31;

    __shared__ int soff[64];
    if (tid < 64) {
        int rc = g_rows[m0 + tid];
        soff[tid] = ((rc >> 5) * MAXS + (rc & 31)) * GG;
    }
    __syncthreads();

    const uint4* Ah = (const uint4*)g_a_hi  + (((size_t)(m0 >> 6) * KC) * 4 + w) * 32 + T;
    const uint4* Al = (const uint4*)g_a_lo  + (((size_t)(m0 >> 6) * KC) * 4 + w) * 32 + T;
    const uint4* Bh = (const uint4*)g_wih_hi + (((size_t)nblk * KC) * 32 + T) * 4;
    const uint4* Bl = (const uint4*)g_wih_lo + (((size_t)nblk * KC) * 32 + T) * 4;

    float acc[8][4];
#pragma unroll
    for (int i = 0; i < 8; i++)
#pragma unroll
        for (int r = 0; r < 4; r++) acc[i][r] = 0.f;

    uint4 ah[2], al[2], bh[2][4], bl[2][4];
#pragma unroll
    for (int q = 0; q < 4; q++) { bh[0][q] = Bh[q]; bl[0][q] = Bl[q]; }
    ah[0] = Ah[0]; al[0] = Al[0];

    for (int kc = 0; kc < KC; kc++) {
        int cur = kc & 1, nxt = cur ^ 1;
        if (kc + 1 < KC) {
            ah[nxt] = Ah[(size_t)(kc + 1) * 128];
            al[nxt] = Al[(size_t)(kc + 1) * 128];
#pragma unroll
            for (int q = 0; q < 4; q++) {
                bh[nxt][q] = Bh[(size_t)(kc + 1) * 128 + q];
                bl[nxt][q] = Bl[(size_t)(kc + 1) * 128 + q];
            }
        }
        const uint32_t* Ahr = (const uint32_t*)&ah[cur];
        const uint32_t* Alr = (const uint32_t*)&al[cur];
        const uint32_t* Bhr = (const uint32_t*)&bh[cur][0];
        const uint32_t* Blr = (const uint32_t*)&bl[cur][0];
#pragma unroll
        for (int nt = 0; nt < 8; nt++) {
            mma16816(acc[nt], Ahr, Bhr + nt * 2);
            mma16816(acc[nt], Ahr, Blr + nt * 2);
            mma16816(acc[nt], Alr, Bhr + nt * 2);
        }
    }

#pragma unroll
    for (int nt = 0; nt < 8; nt++)
#pragma unroll
        for (int r = 0; r < 4; r++) {
            int ml = w * 16 + (T >> 2) + 8 * (r >> 1);
            if (m0 + ml < nrows) {
                int col = nblk * 64 + nt * 8 + 2 * (T & 3) + (r & 1);
                g_xp[(size_t)soff[ml] + col] = acc[nt][r] + b_ih[col] + b_hh[col];
            }
        }
}

// ---------------------------------------------------------------------------
// Kernel 5: one LSTM step via mma.sync. grid 144, block 512.
// warp = gate (w&3) x k-quarter (w>>2, 36 chunks each). 4 partial SMEM bufs.
// ---------------------------------------------------------------------------
__global__ void __launch_bounds__(512) k_step_mma(int t) {
    if (t >= g_maxlen) return;
    int tile = blockIdx.x;
    int tid = threadIdx.x, w = tid >> 5, T = tid & 31;
    int gate = w & 3, kh = w >> 2;          // kh 0..3
    int rb = t & 1, wb = rb ^ 1;

    __shared__ float gsm[4][64 * 33];

    const uint4* Ah = (const uint4*)g_whh_hi + (((size_t)tile * KC + kh * KH4) * 4 + gate) * 32 + T;
    const uint4* Al = (const uint4*)g_whh_lo + (((size_t)tile * KC + kh * KH4) * 4 + gate) * 32 + T;
    const uint4* Bh = (const uint4*)g_hBhi[rb] + (size_t)kh * KH4 * 64 + T * 2;
    const uint4* Bl = (const uint4*)g_hBlo[rb] + (size_t)kh * KH4 * 64 + T * 2;

    float acc[4][4];
#pragma unroll
    for (int i = 0; i < 4; i++)
#pragma unroll
        for (int r = 0; r < 4; r++) acc[i][r] = 0.f;

    uint4 ah[2], al[2], bh[2][2], bl[2][2];
    ah[0] = Ah[0]; al[0] = Al[0];
    bh[0][0] = Bh[0]; bh[0][1] = Bh[1];
    bl[0][0] = Bl[0]; bl[0][1] = Bl[1];

    for (int i = 0; i < KH4; i++) {
        int cur = i & 1, nxt = cur ^ 1;
        if (i + 1 < KH4) {
            size_t ao = (size_t)(i + 1) * 128;
            size_t bo = (size_t)(i + 1) * 64;
            ah[nxt] = Ah[ao];
            al[nxt] = Al[ao];
            bh[nxt][0] = Bh[bo];     bh[nxt][1] = Bh[bo + 1];
            bl[nxt][0] = Bl[bo];     bl[nxt][1] = Bl[bo + 1];
        }
        const uint32_t* Ahr = (const uint32_t*)&ah[cur];
        const uint32_t* Alr = (const uint32_t*)&al[cur];
        const uint32_t* Bhr = (const uint32_t*)&bh[cur][0];
        const uint32_t* Blr = (const uint32_t*)&bl[cur][0];
#pragma unroll
        for (int nt = 0; nt < 4; nt++) {
            mma16816(acc[nt], Ahr, Bhr + nt * 2);
            mma16816(acc[nt], Ahr, Blr + nt * 2);
            mma16816(acc[nt], Alr, Bhr + nt * 2);
        }
    }

    // store partials: each (gate, kh) warp owns a disjoint 16x32 block of gsm[kh]
#pragma unroll
    for (int nt = 0; nt < 4; nt++)
#pragma unroll
        for (int r = 0; r < 4; r++) {
            int rr = (T >> 2) + 8 * (r >> 1);
            int lane = nt * 8 + 2 * (T & 3) + (r & 1);
            gsm[kh][(gate * 16 + rr) * 33 + lane] = acc[nt][r];
        }
    __syncthreads();

    // pointwise + repack h into B-fragment layout (256 thr = 32 lanes x 8 jp)
    if (tid < 256) {
        int lane = tid >> 3, jp = tid & 7;
        int jj0 = jp * 2;
        int Tt = (lane & 7) * 4 + ((jj0 & 7) >> 1);
        int nt = lane >> 3, b = jj0 >> 3;
        int idx = tile * 256 + Tt * 8 + nt * 2 + b;
        if (t < g_len[lane]) {
            float hv[2];
            const float* xp = g_xp + ((size_t)(lane * MAXS + t)) * GG;
#pragma unroll
            for (int q = 0; q < 2; q++) {
                int jj = jj0 + q;
                int j = tile * 16 + jj;
                float gi = gsm[0][(0 * 16 + jj) * 33 + lane] + gsm[1][(0 * 16 + jj) * 33 + lane]
                         + gsm[2][(0 * 16 + jj) * 33 + lane] + gsm[3][(0 * 16 + jj) * 33 + lane]
                         + xp[j];
                float gf = gsm[0][(1 * 16 + jj) * 33 + lane] + gsm[1][(1 * 16 + jj) * 33 + lane]
                         + gsm[2][(1 * 16 + jj) * 33 + lane] + gsm[3][(1 * 16 + jj) * 33 + lane]
                         + xp[HH + j];
                float gg = gsm[0][(2 * 16 + jj) * 33 + lane] + gsm[1][(2 * 16 + jj) * 33 + lane]
                         + gsm[2][(2 * 16 + jj) * 33 + lane] + gsm[3][(2 * 16 + jj) * 33 + lane]
                         + xp[2 * HH + j];
                float go = gsm[0][(3 * 16 + jj) * 33 + lane] + gsm[1][(3 * 16 + jj) * 33 + lane]
                         + gsm[2][(3 * 16 + jj) * 33 + lane] + gsm[3][(3 * 16 + jj) * 33 + lane]
                         + xp[3 * HH + j];
                size_t ci = (size_t)lane * HH + j;
                float cc = sigm(gf) * g_c[ci] + sigm(gi) * tanhf(gg);
                g_c[ci] = cc;
                float h = sigm(go) * tanhf(cc);
                g_h[ci] = h;
                hv[q] = h;
            }
            uint32_t h2, l2; split2(hv[0], hv[1], h2, l2);
            g_hBhi[wb][idx] = h2;
            g_hBlo[wb][idx] = l2;
        } else {
            g_hBhi[wb][idx] = g_hBhi[rb][idx];
            g_hBlo[wb][idx] = g_hBlo[rb][idx];
        }
    }
}

// ---------------------------------------------------------------------------
// Kernel 6: out = [h_left ; h_right] @ W_out^T + b_out
// ---------------------------------------------------------------------------
__global__ void __launch_bounds__(256) k_out(const float* __restrict__ W_out,
                                             const float* __restrict__ b_out,
                                             float* __restrict__ out) {
    int e0 = blockIdx.x * 64;
    int tid = threadIdx.x;
    int eL = tid & 63;
    int bg = tid >> 6;

    __shared__ __align__(16) float Fs[32 * 16];
    __shared__ float Ws[64 * 33];
    float acc[4] = {0.f, 0.f, 0.f, 0.f};

    for (int k0 = 0; k0 < 2 * HH; k0 += 32) {
#pragma unroll
        for (int i = 0; i < 2; i++) {
            int flat = tid + i * 256;
            int b = flat & 15, k = flat >> 4;
            int kk = k0 + k;
            float v = (kk < HH) ? g_h[(size_t)b * HH + kk]
                                : g_h[(size_t)(BB + b) * HH + kk - HH];
            Fs[k * 16 + b] = v;
        }
#pragma unroll
        for (int i = 0; i < 8; i++) {
            int flat = tid + i * 256;
            int e = flat >> 5, k = flat & 31;
            Ws[e * 33 + k] = W_out[(size_t)(e0 + e) * (2 * HH) + k0 + k];
        }
        __syncthreads();
#pragma unroll
        for (int k = 0; k < 32; k++) {
            float wv = Ws[eL * 33 + k];
            float4 f = *(const float4*)&Fs[k * 16 + bg * 4];
            acc[0] += wv * f.x;  acc[1] += wv * f.y;
            acc[2] += wv * f.z;  acc[3] += wv * f.w;
        }
        __syncthreads();
    }
    int e = e0 + eL;
    float bo = b_out[e];
#pragma unroll
    for (int i = 0; i < 4; i++)
        out[(size_t)(bg * 4 + i) * EE + e] = acc[i] + bo;
}

// ---------------------------------------------------------------------------
extern "C" void kernel_launch(void* const* d_in, const int* in_sizes, int n_in,
                              void* d_out, int out_size) {
    const float* feat  = (const float*)d_in[0];
    const int*   mask  = (const int*)  d_in[1];
    const int*   start = (const int*)  d_in[2];
    const int*   end   = (const int*)  d_in[3];
    const float* W_ih  = (const float*)d_in[4];
    const float* W_hh  = (const float*)d_in[5];
    const float* b_ih  = (const float*)d_in[6];
    const float* b_hh  = (const float*)d_in[7];
    const float* W_out = (const float*)d_in[8];
    const float* b_out = (const float*)d_in[9];
    float* out = (float*)d_out;

    k_prep<<<1, 512>>>(mask, start, end);
    k_whhprep<<<dim3(KC, NTH), 128>>>(W_hh);
    k_wihprep<<<dim3(KC, NXB), 128>>>(W_ih);
    k_aprep<<<dim3(9, 1024), 128>>>(feat, start, end);
    k_xp_mma<<<dim3(NXB, 16), 128>>>(b_ih, b_hh);
    for (int t = 0; t < NSTEPS; t++)
        k_step_mma<<<NTH, 512>>>(t);
    k_out<<<EE / 64, 256>>>(W_out, b_out, out);
}